// round 16
// baseline (speedup 1.0000x reference)
#include <cuda_runtime.h>
#include <cuda_bf16.h>
#include <math.h>
#include <stdint.h>

#define Bdim 64
#define Sdim 512
#define Fdim 512
#define Hdim 1024

// ---------------- scratch (static device globals; no runtime allocation) ----
__device__ float g_xp[(size_t)Bdim * Sdim * Hdim];    // xp layer 0 (from x)
__device__ __nv_bfloat16 g_hh1[2][Bdim * Hdim];       // layer-0 hidden hi, [b][k]
__device__ __nv_bfloat16 g_hl1[2][Bdim * Hdim];       // layer-0 hidden lo
__device__ __nv_bfloat16 g_hh2[2][Bdim * Hdim];       // layer-1 hidden hi
__device__ __nv_bfloat16 g_hl2[2][Bdim * Hdim];       // layer-1 hidden lo
__device__ unsigned g_bar_cnt = 0; __device__ unsigned g_bar_gen = 0;

static __device__ __forceinline__ unsigned smem_u32(const void* p) {
    return (unsigned)__cvta_generic_to_shared(p);
}

// ---------------- cohort barrier: scoped release/acquire --------------------
static __device__ __forceinline__ void grid_sync_p(unsigned* cnt, unsigned* gen,
                                                   int nblocks) {
    __syncthreads();
    if (threadIdx.x == 0) {
        unsigned g;
        asm volatile("ld.relaxed.gpu.global.u32 %0, [%1];" : "=r"(g) : "l"(gen));
        unsigned old;
        asm volatile("atom.acq_rel.gpu.global.add.u32 %0, [%1], 1;"
                     : "=r"(old) : "l"(cnt) : "memory");
        if (old == (unsigned)(nblocks - 1)) {
            asm volatile("st.relaxed.gpu.global.u32 [%0], %1;"
                         :: "l"(cnt), "r"(0u) : "memory");
            asm volatile("st.release.gpu.global.u32 [%0], %1;"
                         :: "l"(gen), "r"(g + 1) : "memory");
        } else {
            unsigned cur;
            do {
                asm volatile("ld.acquire.gpu.global.u32 %0, [%1];"
                             : "=r"(cur) : "l"(gen) : "memory");
            } while (cur == g);
        }
    }
    __syncthreads();
}

// ---------------- mma.sync helpers ------------------------------------------
static __device__ __forceinline__ void ldsm_x4(uint32_t addr, uint32_t* r) {
    asm volatile("ldmatrix.sync.aligned.m8n8.x4.shared.b16 {%0,%1,%2,%3}, [%4];"
                 : "=r"(r[0]), "=r"(r[1]), "=r"(r[2]), "=r"(r[3]) : "r"(addr));
}
static __device__ __forceinline__ void mma16816(float* c, const uint32_t* a,
                                                const uint32_t* b) {
    asm volatile("mma.sync.aligned.m16n8k16.row.col.f32.bf16.bf16.f32 "
                 "{%0,%1,%2,%3}, {%4,%5,%6,%7}, {%8,%9}, {%0,%1,%2,%3};"
                 : "+f"(c[0]), "+f"(c[1]), "+f"(c[2]), "+f"(c[3])
                 : "r"(a[0]), "r"(a[1]), "r"(a[2]), "r"(a[3]),
                   "r"(b[0]), "r"(b[1]));
}
static __device__ __forceinline__ void split_bf16(float4 v, uint2& hi, uint2& lo) {
    __nv_bfloat162 h01 = __floats2bfloat162_rn(v.x, v.y);
    __nv_bfloat162 h23 = __floats2bfloat162_rn(v.z, v.w);
    __nv_bfloat162 l01 = __floats2bfloat162_rn(v.x - __low2float(h01),
                                               v.y - __high2float(h01));
    __nv_bfloat162 l23 = __floats2bfloat162_rn(v.z - __low2float(h23),
                                               v.w - __high2float(h23));
    hi = make_uint2(*(unsigned*)&h01, *(unsigned*)&h23);
    lo = make_uint2(*(unsigned*)&l01, *(unsigned*)&l23);
}
static __device__ __forceinline__ void split2_bf16(float v0, float v1,
                                                   unsigned& hi, unsigned& lo) {
    __nv_bfloat162 h = __floats2bfloat162_rn(v0, v1);
    __nv_bfloat162 l = __floats2bfloat162_rn(v0 - __low2float(h),
                                             v1 - __high2float(h));
    hi = *(unsigned*)&h;
    lo = *(unsigned*)&l;
}

// ============================================================================
// xproj kernel for layer-0 xp (proven R7 body): out = A@Wt^T + ba + bb
// ============================================================================
#define SW128(o) ((o) ^ (((o) >> 3) & 0x70))
#define XP_OFF_BIAS 0
#define XP_OFF_AH   1024
#define XP_OFF_AL   (XP_OFF_AH + 16384)
#define XP_OFF_BH   (XP_OFF_AL + 16384)
#define XP_OFF_BL   (XP_OFF_BH + 16384)
#define XP_SMEM     (XP_OFF_BL + 16384)

static __device__ __forceinline__ uint32_t lm_addr(uint32_t base, int r, int ck) {
    return base + r * 128 + ((ck ^ (r & 7)) << 4);
}

template <int K>
__global__ void __launch_bounds__(256, 2) xproj_mma_kernel(
    const float* __restrict__ A, const float* __restrict__ Wt,
    const float* __restrict__ ba, const float* __restrict__ bb,
    float* __restrict__ out)
{
    extern __shared__ __align__(1024) char xsm[];
    const uint32_t sb = smem_u32(xsm);
    const int tid = threadIdx.x;
    const int wid = tid >> 5;
    const int lane = tid & 31;
    const int wm = wid & 3;
    const int wn = wid >> 2;
    const int m0 = blockIdx.y * 128;
    const int n0 = blockIdx.x * 128;

    float* sbias = (float*)(xsm + XP_OFF_BIAS);
    if (tid < 128) sbias[tid] = ba[n0 + tid] + bb[n0 + tid];

    float acc[2][8][4];
#pragma unroll
    for (int mt = 0; mt < 2; mt++)
#pragma unroll
        for (int nt = 0; nt < 8; nt++)
#pragma unroll
            for (int i = 0; i < 4; i++) acc[mt][nt][i] = 0.0f;

    const int NKT = K / 64;
#pragma unroll 1
    for (int kt = 0; kt < NKT; kt++) {
        __syncthreads();
        const float* Asrc = A + (size_t)m0 * K + kt * 64;
        const float* Bsrc = Wt + (size_t)n0 * K + kt * 64;
#pragma unroll
        for (int r = 0; r < 8; r++) {
            int idx = r * 256 + tid;
            int row = idx >> 4;
            int c4 = idx & 15;
            int sw = SW128(row * 128 + c4 * 8);
            uint2 hi, lo;
            split_bf16(*(const float4*)&Asrc[(size_t)row * K + c4 * 4], hi, lo);
            *(uint2*)(xsm + XP_OFF_AH + sw) = hi;
            *(uint2*)(xsm + XP_OFF_AL + sw) = lo;
            split_bf16(*(const float4*)&Bsrc[(size_t)row * K + c4 * 4], hi, lo);
            *(uint2*)(xsm + XP_OFF_BH + sw) = hi;
            *(uint2*)(xsm + XP_OFF_BL + sw) = lo;
        }
        __syncthreads();

        const int asub = lane >> 3;
        const int arow = (asub & 1) * 8 + (lane & 7);
        const int ack = asub >> 1;
        const int brow = ((lane >> 4) & 1) * 8 + (lane & 7);
        const int bck = (lane >> 3) & 1;

#pragma unroll
        for (int p = 0; p < 3; p++) {
            uint32_t aBase = sb + ((p == 2) ? XP_OFF_AL : XP_OFF_AH);
            uint32_t bBase = sb + ((p == 1) ? XP_OFF_BL : XP_OFF_BH);
#pragma unroll
            for (int kk = 0; kk < 4; kk++) {
                uint32_t afrag[2][4], bfrag[8][2];
#pragma unroll
                for (int mt = 0; mt < 2; mt++)
                    ldsm_x4(lm_addr(aBase, wm * 32 + mt * 16 + arow, kk * 2 + ack),
                            afrag[mt]);
#pragma unroll
                for (int np = 0; np < 4; np++) {
                    uint32_t r4[4];
                    ldsm_x4(lm_addr(bBase, wn * 64 + np * 16 + brow, kk * 2 + bck), r4);
                    bfrag[np * 2][0] = r4[0]; bfrag[np * 2][1] = r4[1];
                    bfrag[np * 2 + 1][0] = r4[2]; bfrag[np * 2 + 1][1] = r4[3];
                }
#pragma unroll
                for (int mt = 0; mt < 2; mt++)
#pragma unroll
                    for (int nt = 0; nt < 8; nt++)
                        mma16816(acc[mt][nt], afrag[mt], bfrag[nt]);
            }
        }
    }

#pragma unroll
    for (int mt = 0; mt < 2; mt++) {
#pragma unroll
        for (int nt = 0; nt < 8; nt++) {
            int m = m0 + wm * 32 + mt * 16 + (lane >> 2);
            int nl = wn * 64 + nt * 8 + (lane & 3) * 2;
            float2 o0, o1;
            o0.x = acc[mt][nt][0] + sbias[nl];
            o0.y = acc[mt][nt][1] + sbias[nl + 1];
            o1.x = acc[mt][nt][2] + sbias[nl];
            o1.y = acc[mt][nt][3] + sbias[nl + 1];
            *(float2*)&out[(size_t)m * Hdim + n0 + nl] = o0;
            *(float2*)&out[(size_t)(m + 8) * Hdim + n0 + nl] = o1;
        }
    }
}

// ============================================================================
// Merged dual-layer recurrence: ONE cohort, 64 CTAs x 256 threads.
// CTA owns j-range [16i, 16i+16) for BOTH layers. Loop s = 0..512:
//   s < 512: h1[s+1] = tanh(xp0[s] + Whh0 . h1[s])
//   s >= 1 : h2[s-1] = tanh(bias1 + Wih1 . h1[s] + Whh1 . h2[s-2])
//            (h1[s] IS layer-0's output at time s-1 -> correct skew)
// 16 phases x 128-k: phases 0-7 stream h1[s] (feeds Whh0 AND Wih1 parts),
// phases 8-15 stream h2[s-2] (Whh1 part). Whh0 + Whh1 frags in REGISTERS,
// Wih1 in SMEM. 4x32KB stage buffers, depth-3 prefetch, 1 sync/phase.
// No inter-layer counter, no xp2 buffer, one 64-CTA barrier per step.
// ============================================================================
#define RNN_SMEM_BYTES 196608
#define M_WX_H   0          /* Wih1 hi 32K, lo at +32768 */
#define M_WX_L   32768
#define M_BUF(i) (65536 + (i) * 32768)

// stage one 128-k chunk of h (hi+lo) into a 32KB buffer.
static __device__ __forceinline__ void stage_h128(
    const __nv_bfloat16* __restrict__ hh, const __nv_bfloat16* __restrict__ hl,
    int c, char* dst, int tid)
{
#pragma unroll
    for (int r = 0; r < 4; r++) {
        int idx = r * 256 + tid;              // 0..1023
        int b = idx >> 4;                     // 0..63
        int g = idx & 15;                     // granule within 256B row
        int ph = (g & 8) | ((g ^ (b & 7)) & 7);
        uint32_t d = smem_u32(dst + b * 256 + ph * 16);
        const __nv_bfloat16* s = hh + b * Hdim + c * 128 + g * 8;
        asm volatile("cp.async.cg.shared.global [%0], [%1], 16;" ::"r"(d), "l"(s));
        const __nv_bfloat16* s2 = hl + b * Hdim + c * 128 + g * 8;
        asm volatile("cp.async.cg.shared.global [%0], [%1], 16;"
                     ::"r"(d + 16384), "l"(s2));
    }
}

// stage chunk q of the 16-chunk stream (q<8: h1 chunk q; q>=8: h2 chunk q-8)
static __device__ __forceinline__ void stage_q(
    const __nv_bfloat16* hh1, const __nv_bfloat16* hl1,
    const __nv_bfloat16* hh2, const __nv_bfloat16* hl2,
    int q, char* dst, int tid)
{
    if (q < 8) stage_h128(hh1, hl1, q, dst, tid);
    else       stage_h128(hh2, hl2, q - 8, dst, tid);
}

// load a 16x1024 W matrix into temp swizzled SMEM (rows 2048B, hi/lo)
static __device__ __forceinline__ void load_w_temp(
    const float* __restrict__ W, int j0, char* smraw, int hioff, int looff,
    int tid)
{
    for (int i = tid; i < 4096; i += 256) {
        int j = i >> 8;
        int col4 = i & 255;
        uint2 hi, lo;
        split_bf16(*(const float4*)&W[(size_t)(j0 + j) * Hdim + col4 * 4], hi, lo);
        int g = col4 >> 1;
        int off = j * 2048 + ((g ^ (j & 7)) << 4) + (col4 & 1) * 8;
        *(uint2*)(smraw + hioff + off) = hi;
        *(uint2*)(smraw + looff + off) = lo;
    }
}

__global__ void __launch_bounds__(256) rnn_merged_kernel(
    const float* __restrict__ xp0, const float* __restrict__ Whh0,
    const float* __restrict__ Wih1, const float* __restrict__ bi1,
    const float* __restrict__ bh1, const float* __restrict__ Whh1)
{
    extern __shared__ __align__(1024) char smraw[];
    const int tid = threadIdx.x;
    const int bid = blockIdx.x;
    const int wid = tid >> 5;
    const int lane = tid & 31;
    const int j0 = bid * 16;

    // ldmatrix lane mappings
    const int asub = lane >> 3;
    const int arow = (asub & 1) * 8 + (lane & 7);
    const int ack = asub >> 1;
    const int brow = ((lane >> 4) & 1) * 8 + (lane & 7);
    const int bck = (lane >> 3) & 1;
    // epilogue: 4 outputs per thread
    const int eb = tid >> 2;
    const int ej = (tid & 3) * 4;

    float* p_r0 = (float*)(smraw + M_BUF(0));   // rec0 partials alias buf0
    float* p_r1 = (float*)(smraw + M_BUF(1));   // rec1 partials alias buf1

    // ---- init: Wih1 -> persistent SMEM ----
    load_w_temp(Wih1, j0, smraw, M_WX_H, M_WX_L, tid);
    // Whh0 -> temp (bufs 2/3), then registers
    load_w_temp(Whh0, j0, smraw, M_BUF(2), M_BUF(3), tid);
    __syncthreads();
    uint32_t wRh[8][4], wRl[8][4];
#pragma unroll
    for (int c = 0; c < 8; c++) {
        int gB = (c * 8 + wid) * 2 + bck;
        uint32_t sw = (uint32_t)((gB ^ (brow & 7)) << 4);
        ldsm_x4(smem_u32(smraw + M_BUF(2)) + brow * 2048 + sw, wRh[c]);
        ldsm_x4(smem_u32(smraw + M_BUF(3)) + brow * 2048 + sw, wRl[c]);
    }
    __syncthreads();
    // Whh1 -> temp, then registers
    load_w_temp(Whh1, j0, smraw, M_BUF(2), M_BUF(3), tid);
    __syncthreads();
    uint32_t wSh[8][4], wSl[8][4];
#pragma unroll
    for (int c = 0; c < 8; c++) {
        int gB = (c * 8 + wid) * 2 + bck;
        uint32_t sw = (uint32_t)((gB ^ (brow & 7)) << 4);
        ldsm_x4(smem_u32(smraw + M_BUF(2)) + brow * 2048 + sw, wSh[c]);
        ldsm_x4(smem_u32(smraw + M_BUF(3)) + brow * 2048 + sw, wSl[c]);
    }

    // zero h1[0] (slot 0) and h2 BOTH slots (slot 1 = h2[-1]; slot 0 is read
    // as dummy input during step 0 phases 8-15) for owned columns
    if (tid < 64) {
        uint4 z = make_uint4(0, 0, 0, 0);
        *(uint4*)&g_hh1[0][(size_t)tid * Hdim + j0] = z;
        *(uint4*)&g_hh1[0][(size_t)tid * Hdim + j0 + 8] = z;
        *(uint4*)&g_hl1[0][(size_t)tid * Hdim + j0] = z;
        *(uint4*)&g_hl1[0][(size_t)tid * Hdim + j0 + 8] = z;
#pragma unroll
        for (int sl = 0; sl < 2; sl++) {
            *(uint4*)&g_hh2[sl][(size_t)tid * Hdim + j0] = z;
            *(uint4*)&g_hh2[sl][(size_t)tid * Hdim + j0 + 8] = z;
            *(uint4*)&g_hl2[sl][(size_t)tid * Hdim + j0] = z;
            *(uint4*)&g_hl2[sl][(size_t)tid * Hdim + j0 + 8] = z;
        }
    }
    float bias1[4];
#pragma unroll
    for (int i = 0; i < 4; i++)
        bias1[i] = bi1[j0 + ej + i] + bh1[j0 + ej + i];

    grid_sync_p(&g_bar_cnt, &g_bar_gen, 64);

#pragma unroll 1
    for (int s = 0; s <= Sdim; s++) {
        const __nv_bfloat16* hh1_in = g_hh1[s & 1];
        const __nv_bfloat16* hl1_in = g_hl1[s & 1];
        const __nv_bfloat16* hh2_in = g_hh2[s & 1];         // h2[s-2]
        const __nv_bfloat16* hl2_in = g_hl2[s & 1];
        __nv_bfloat16* hh1_out = g_hh1[(s + 1) & 1];
        __nv_bfloat16* hl1_out = g_hl1[(s + 1) & 1];
        __nv_bfloat16* hh2_out = g_hh2[(s + 1) & 1];        // h2[s-1]
        __nv_bfloat16* hl2_out = g_hl2[(s + 1) & 1];

        int tt = (s < Sdim) ? s : Sdim - 1;
        float4 xpv = *(const float4*)&xp0[((size_t)eb * Sdim + tt) * Hdim
                                          + j0 + ej];

        float accR[4][2][4], accS[4][2][4];
#pragma unroll
        for (int mt = 0; mt < 4; mt++)
#pragma unroll
            for (int nt = 0; nt < 2; nt++)
#pragma unroll
                for (int i = 0; i < 4; i++) {
                    accR[mt][nt][i] = 0.0f;
                    accS[mt][nt][i] = 0.0f;
                }

        stage_q(hh1_in, hl1_in, hh2_in, hl2_in, 0, smraw + M_BUF(0), tid);
        asm volatile("cp.async.commit_group;");
        stage_q(hh1_in, hl1_in, hh2_in, hl2_in, 1, smraw + M_BUF(1), tid);
        asm volatile("cp.async.commit_group;");
        stage_q(hh1_in, hl1_in, hh2_in, hl2_in, 2, smraw + M_BUF(2), tid);
        asm volatile("cp.async.commit_group;");

#pragma unroll
        for (int c = 0; c < 16; c++) {
            if (c < 14)       asm volatile("cp.async.wait_group 2;");
            else if (c == 14) asm volatile("cp.async.wait_group 1;");
            else              asm volatile("cp.async.wait_group 0;");
            __syncthreads();   // chunk c visible; orders phase c-1 reads of
                               // buf (c+3)&3 before its restage below

            const uint32_t shb = smem_u32(smraw + M_BUF(c & 3));
            const uint32_t slb = shb + 16384;

            uint32_t ah[4][4], al[4][4];
            int gA = wid * 2 + ack;
#pragma unroll
            for (int mt = 0; mt < 4; mt++) {
                int row = mt * 16 + arow;
                uint32_t ph = (uint32_t)((gA & 8) | ((gA ^ (row & 7)) & 7)) << 4;
                ldsm_x4(shb + row * 256 + ph, ah[mt]);
                ldsm_x4(slb + row * 256 + ph, al[mt]);
            }

            if (c < 8) {
                // rec0 (regs) + Wih1 part of rec1 (SMEM)
                int gB = (c * 8 + wid) * 2 + bck;
                uint32_t bsw = (uint32_t)((gB ^ (brow & 7)) << 4);
                uint32_t xh[4], xl[4];
                ldsm_x4(smem_u32(smraw + M_WX_H) + brow * 2048 + bsw, xh);
                ldsm_x4(smem_u32(smraw + M_WX_L) + brow * 2048 + bsw, xl);
#pragma unroll
                for (int mt = 0; mt < 4; mt++) {
                    mma16816(accR[mt][0], ah[mt], &wRh[c][0]);
                    mma16816(accR[mt][1], ah[mt], &wRh[c][2]);
                    mma16816(accR[mt][0], ah[mt], &wRl[c][0]);
                    mma16816(accR[mt][1], ah[mt], &wRl[c][2]);
                    mma16816(accR[mt][0], al[mt], &wRh[c][0]);
                    mma16816(accR[mt][1], al[mt], &wRh[c][2]);
                    mma16816(accS[mt][0], ah[mt], &xh[0]);
                    mma16816(accS[mt][1], ah[mt], &xh[2]);
                    mma16816(accS[mt][0], ah[mt], &xl[0]);
                    mma16816(accS[mt][1], ah[mt], &xl[2]);
                    mma16816(accS[mt][0], al[mt], &xh[0]);
                    mma16816(accS[mt][1], al[mt], &xh[2]);
                }
            } else {
                // Whh1 part of rec1 (regs)
                const int p = c - 8;
#pragma unroll
                for (int mt = 0; mt < 4; mt++) {
                    mma16816(accS[mt][0], ah[mt], &wSh[p][0]);
                    mma16816(accS[mt][1], ah[mt], &wSh[p][2]);
                    mma16816(accS[mt][0], ah[mt], &wSl[p][0]);
                    mma16816(accS[mt][1], ah[mt], &wSl[p][2]);
                    mma16816(accS[mt][0], al[mt], &wSh[p][0]);
                    mma16816(accS[mt][1], al[mt], &wSh[p][2]);
                }
            }
            if (c + 3 < 16) {
                stage_q(hh1_in, hl1_in, hh2_in, hl2_in, c + 3,
                        smraw + M_BUF((c + 3) & 3), tid);
                asm volatile("cp.async.commit_group;");
            }
        }

        // partials (bufs 0/1 free: all warps are past the phase-15 top sync)
#pragma unroll
        for (int mt = 0; mt < 4; mt++)
#pragma unroll
            for (int nt = 0; nt < 2; nt++) {
                int b = mt * 16 + (lane >> 2);
                int j = nt * 8 + (lane & 3) * 2;
                *(float2*)&p_r0[wid * 1024 + b * 16 + j] =
                    make_float2(accR[mt][nt][0], accR[mt][nt][1]);
                *(float2*)&p_r0[wid * 1024 + (b + 8) * 16 + j] =
                    make_float2(accR[mt][nt][2], accR[mt][nt][3]);
                *(float2*)&p_r1[wid * 1024 + b * 16 + j] =
                    make_float2(accS[mt][nt][0], accS[mt][nt][1]);
                *(float2*)&p_r1[wid * 1024 + (b + 8) * 16 + j] =
                    make_float2(accS[mt][nt][2], accS[mt][nt][3]);
            }
        __syncthreads();

        {
            int o = tid * 4;
            float4 sr = *(const float4*)&p_r0[o];
            float4 ss = *(const float4*)&p_r1[o];
#pragma unroll
            for (int w = 1; w < 8; w++) {
                float4 q = *(const float4*)&p_r0[w * 1024 + o];
                sr.x += q.x; sr.y += q.y; sr.z += q.z; sr.w += q.w;
                float4 q2 = *(const float4*)&p_r1[w * 1024 + o];
                ss.x += q2.x; ss.y += q2.y; ss.z += q2.z; ss.w += q2.w;
            }
            // h1[s+1] = tanh(xp0[s] + Whh0.h1[s])
            if (s < Sdim) {
                float v0 = tanhf(sr.x + xpv.x);
                float v1 = tanhf(sr.y + xpv.y);
                float v2 = tanhf(sr.z + xpv.z);
                float v3 = tanhf(sr.w + xpv.w);
                unsigned h01, l01, h23, l23;
                split2_bf16(v0, v1, h01, l01);
                split2_bf16(v2, v3, h23, l23);
                size_t ho = (size_t)eb * Hdim + j0 + ej;
                *(uint2*)&hh1_out[ho] = make_uint2(h01, h23);
                *(uint2*)&hl1_out[ho] = make_uint2(l01, l23);
            }
            // h2[s-1] = tanh(bias1 + Wih1.h1[s] + Whh1.h2[s-2])
            if (s >= 1) {
                float v0 = tanhf(ss.x + bias1[0]);
                float v1 = tanhf(ss.y + bias1[1]);
                float v2 = tanhf(ss.z + bias1[2]);
                float v3 = tanhf(ss.w + bias1[3]);
                unsigned h01, l01, h23, l23;
                split2_bf16(v0, v1, h01, l01);
                split2_bf16(v2, v3, h23, l23);
                size_t ho = (size_t)eb * Hdim + j0 + ej;
                *(uint2*)&hh2_out[ho] = make_uint2(h01, h23);
                *(uint2*)&hl2_out[ho] = make_uint2(l01, l23);
            }
        }
        grid_sync_p(&g_bar_cnt, &g_bar_gen, 64);
    }
}

// ============================================================================
// Final FC + sigmoid: h_last = h2[511], written at s=512 into slot (512+1)&1=1
// ============================================================================
__global__ void fc_kernel(const __nv_bfloat16* __restrict__ hh,
                          const __nv_bfloat16* __restrict__ hl,
                          const float* __restrict__ fcw,
                          const float* __restrict__ fcb,
                          float* __restrict__ out)
{
    __shared__ float red[8];
    int b = blockIdx.x, tid = threadIdx.x;
    float s = 0.0f;
    for (int k = tid; k < Hdim; k += 256) {
        float h = __bfloat162float(hh[b * Hdim + k]) +
                  __bfloat162float(hl[b * Hdim + k]);
        s += h * fcw[k];
    }
#pragma unroll
    for (int o = 16; o; o >>= 1) s += __shfl_xor_sync(0xFFFFFFFFu, s, o);
    if ((tid & 31) == 0) red[tid >> 5] = s;
    __syncthreads();
    if (tid == 0) {
        float tot = 0.0f;
#pragma unroll
        for (int i = 0; i < 8; i++) tot += red[i];
        float logit = tot + fcb[0];
        out[b] = 1.0f / (1.0f + expf(-logit));
    }
}

// ============================================================================
extern "C" void kernel_launch(void* const* d_in, const int* in_sizes, int n_in,
                              void* d_out, int out_size)
{
    const float* x     = (const float*)d_in[0];
    const float* W_ih0 = (const float*)d_in[1];
    const float* W_hh0 = (const float*)d_in[2];
    const float* b_ih0 = (const float*)d_in[3];
    const float* b_hh0 = (const float*)d_in[4];
    const float* W_ih1 = (const float*)d_in[5];
    const float* W_hh1 = (const float*)d_in[6];
    const float* b_ih1 = (const float*)d_in[7];
    const float* b_hh1 = (const float*)d_in[8];
    const float* fc_w  = (const float*)d_in[9];
    const float* fc_b  = (const float*)d_in[10];
    float* out = (float*)d_out;

    float* xp;
    __nv_bfloat16 *hh2, *hl2;
    cudaGetSymbolAddress((void**)&xp, g_xp);
    cudaGetSymbolAddress((void**)&hh2, g_hh2);
    cudaGetSymbolAddress((void**)&hl2, g_hl2);

    cudaFuncSetAttribute(rnn_merged_kernel,
                         cudaFuncAttributeMaxDynamicSharedMemorySize,
                         RNN_SMEM_BYTES);
    cudaFuncSetAttribute(xproj_mma_kernel<Fdim>,
                         cudaFuncAttributeMaxDynamicSharedMemorySize, XP_SMEM);

    dim3 xgrid(8, 256);
    // layer-0 xp: rows m = b*S + t -> xp[(b*S+t)*H + j]
    xproj_mma_kernel<Fdim><<<xgrid, 256, XP_SMEM>>>(x, W_ih0, b_ih0, b_hh0, xp);
    // merged dual-layer recurrence (single cohort, 64 CTAs)
    rnn_merged_kernel<<<64, 256, RNN_SMEM_BYTES>>>(
        xp, W_hh0, W_ih1, b_ih1, b_hh1, W_hh1);
    // head: h2[511] written at s=512 into slot (512+1)&1 = 1
    fc_kernel<<<64, 256>>>(hh2 + Bdim * Hdim, hl2 + Bdim * Hdim, fc_w, fc_b, out);
}

// round 17
// speedup vs baseline: 1.4967x; 1.4967x over previous
#include <cuda_runtime.h>
#include <cuda_bf16.h>
#include <math.h>
#include <stdint.h>

#define Bdim 64
#define Sdim 512
#define Fdim 512
#define Hdim 1024

// ---------------- scratch (static device globals; no runtime allocation) ----
__device__ float g_xp[(size_t)Bdim * Sdim * Hdim];    // xp layer 0 (from x)
__device__ __nv_bfloat16 g_hh1[2][Bdim * Hdim];       // layer-0 hidden hi, [b][k]
__device__ __nv_bfloat16 g_hl1[2][Bdim * Hdim];       // layer-0 hidden lo
__device__ __nv_bfloat16 g_hh2[2][Bdim * Hdim];       // layer-1 hidden hi
__device__ __nv_bfloat16 g_hl2[2][Bdim * Hdim];       // layer-1 hidden lo
__device__ unsigned g_bar_cnt = 0; __device__ unsigned g_bar_gen = 0;

static __device__ __forceinline__ unsigned smem_u32(const void* p) {
    return (unsigned)__cvta_generic_to_shared(p);
}

// ---------------- grid barrier: scoped release/acquire ----------------------
static __device__ __forceinline__ void grid_sync_p(unsigned* cnt, unsigned* gen,
                                                   int nblocks) {
    __syncthreads();
    if (threadIdx.x == 0) {
        unsigned g;
        asm volatile("ld.relaxed.gpu.global.u32 %0, [%1];" : "=r"(g) : "l"(gen));
        unsigned old;
        asm volatile("atom.acq_rel.gpu.global.add.u32 %0, [%1], 1;"
                     : "=r"(old) : "l"(cnt) : "memory");
        if (old == (unsigned)(nblocks - 1)) {
            asm volatile("st.relaxed.gpu.global.u32 [%0], %1;"
                         :: "l"(cnt), "r"(0u) : "memory");
            asm volatile("st.release.gpu.global.u32 [%0], %1;"
                         :: "l"(gen), "r"(g + 1) : "memory");
        } else {
            unsigned cur;
            do {
                asm volatile("ld.acquire.gpu.global.u32 %0, [%1];"
                             : "=r"(cur) : "l"(gen) : "memory");
            } while (cur == g);
        }
    }
    __syncthreads();
}

// ---------------- mma.sync helpers ------------------------------------------
static __device__ __forceinline__ void ldsm_x4(uint32_t addr, uint32_t* r) {
    asm volatile("ldmatrix.sync.aligned.m8n8.x4.shared.b16 {%0,%1,%2,%3}, [%4];"
                 : "=r"(r[0]), "=r"(r[1]), "=r"(r[2]), "=r"(r[3]) : "r"(addr));
}
static __device__ __forceinline__ void mma16816(float* c, const uint32_t* a,
                                                const uint32_t* b) {
    asm volatile("mma.sync.aligned.m16n8k16.row.col.f32.bf16.bf16.f32 "
                 "{%0,%1,%2,%3}, {%4,%5,%6,%7}, {%8,%9}, {%0,%1,%2,%3};"
                 : "+f"(c[0]), "+f"(c[1]), "+f"(c[2]), "+f"(c[3])
                 : "r"(a[0]), "r"(a[1]), "r"(a[2]), "r"(a[3]),
                   "r"(b[0]), "r"(b[1]));
}
static __device__ __forceinline__ void split_bf16(float4 v, uint2& hi, uint2& lo) {
    __nv_bfloat162 h01 = __floats2bfloat162_rn(v.x, v.y);
    __nv_bfloat162 h23 = __floats2bfloat162_rn(v.z, v.w);
    __nv_bfloat162 l01 = __floats2bfloat162_rn(v.x - __low2float(h01),
                                               v.y - __high2float(h01));
    __nv_bfloat162 l23 = __floats2bfloat162_rn(v.z - __low2float(h23),
                                               v.w - __high2float(h23));
    hi = make_uint2(*(unsigned*)&h01, *(unsigned*)&h23);
    lo = make_uint2(*(unsigned*)&l01, *(unsigned*)&l23);
}
static __device__ __forceinline__ void split2_bf16(float v0, float v1,
                                                   unsigned& hi, unsigned& lo) {
    __nv_bfloat162 h = __floats2bfloat162_rn(v0, v1);
    __nv_bfloat162 l = __floats2bfloat162_rn(v0 - __low2float(h),
                                             v1 - __high2float(h));
    hi = *(unsigned*)&h;
    lo = *(unsigned*)&l;
}

// ============================================================================
// xproj kernel for layer-0 xp (proven R7 body): out = A@Wt^T + ba + bb
// ============================================================================
#define SW128(o) ((o) ^ (((o) >> 3) & 0x70))
#define XP_OFF_BIAS 0
#define XP_OFF_AH   1024
#define XP_OFF_AL   (XP_OFF_AH + 16384)
#define XP_OFF_BH   (XP_OFF_AL + 16384)
#define XP_OFF_BL   (XP_OFF_BH + 16384)
#define XP_SMEM     (XP_OFF_BL + 16384)

static __device__ __forceinline__ uint32_t lm_addr(uint32_t base, int r, int ck) {
    return base + r * 128 + ((ck ^ (r & 7)) << 4);
}

template <int K>
__global__ void __launch_bounds__(256, 2) xproj_mma_kernel(
    const float* __restrict__ A, const float* __restrict__ Wt,
    const float* __restrict__ ba, const float* __restrict__ bb,
    float* __restrict__ out)
{
    extern __shared__ __align__(1024) char xsm[];
    const uint32_t sb = smem_u32(xsm);
    const int tid = threadIdx.x;
    const int wid = tid >> 5;
    const int lane = tid & 31;
    const int wm = wid & 3;
    const int wn = wid >> 2;
    const int m0 = blockIdx.y * 128;
    const int n0 = blockIdx.x * 128;

    float* sbias = (float*)(xsm + XP_OFF_BIAS);
    if (tid < 128) sbias[tid] = ba[n0 + tid] + bb[n0 + tid];

    float acc[2][8][4];
#pragma unroll
    for (int mt = 0; mt < 2; mt++)
#pragma unroll
        for (int nt = 0; nt < 8; nt++)
#pragma unroll
            for (int i = 0; i < 4; i++) acc[mt][nt][i] = 0.0f;

    const int NKT = K / 64;
#pragma unroll 1
    for (int kt = 0; kt < NKT; kt++) {
        __syncthreads();
        const float* Asrc = A + (size_t)m0 * K + kt * 64;
        const float* Bsrc = Wt + (size_t)n0 * K + kt * 64;
#pragma unroll
        for (int r = 0; r < 8; r++) {
            int idx = r * 256 + tid;
            int row = idx >> 4;
            int c4 = idx & 15;
            int sw = SW128(row * 128 + c4 * 8);
            uint2 hi, lo;
            split_bf16(*(const float4*)&Asrc[(size_t)row * K + c4 * 4], hi, lo);
            *(uint2*)(xsm + XP_OFF_AH + sw) = hi;
            *(uint2*)(xsm + XP_OFF_AL + sw) = lo;
            split_bf16(*(const float4*)&Bsrc[(size_t)row * K + c4 * 4], hi, lo);
            *(uint2*)(xsm + XP_OFF_BH + sw) = hi;
            *(uint2*)(xsm + XP_OFF_BL + sw) = lo;
        }
        __syncthreads();

        const int asub = lane >> 3;
        const int arow = (asub & 1) * 8 + (lane & 7);
        const int ack = asub >> 1;
        const int brow = ((lane >> 4) & 1) * 8 + (lane & 7);
        const int bck = (lane >> 3) & 1;

#pragma unroll
        for (int p = 0; p < 3; p++) {
            uint32_t aBase = sb + ((p == 2) ? XP_OFF_AL : XP_OFF_AH);
            uint32_t bBase = sb + ((p == 1) ? XP_OFF_BL : XP_OFF_BH);
#pragma unroll
            for (int kk = 0; kk < 4; kk++) {
                uint32_t afrag[2][4], bfrag[8][2];
#pragma unroll
                for (int mt = 0; mt < 2; mt++)
                    ldsm_x4(lm_addr(aBase, wm * 32 + mt * 16 + arow, kk * 2 + ack),
                            afrag[mt]);
#pragma unroll
                for (int np = 0; np < 4; np++) {
                    uint32_t r4[4];
                    ldsm_x4(lm_addr(bBase, wn * 64 + np * 16 + brow, kk * 2 + bck), r4);
                    bfrag[np * 2][0] = r4[0]; bfrag[np * 2][1] = r4[1];
                    bfrag[np * 2 + 1][0] = r4[2]; bfrag[np * 2 + 1][1] = r4[3];
                }
#pragma unroll
                for (int mt = 0; mt < 2; mt++)
#pragma unroll
                    for (int nt = 0; nt < 8; nt++)
                        mma16816(acc[mt][nt], afrag[mt], bfrag[nt]);
            }
        }
    }

#pragma unroll
    for (int mt = 0; mt < 2; mt++) {
#pragma unroll
        for (int nt = 0; nt < 8; nt++) {
            int m = m0 + wm * 32 + mt * 16 + (lane >> 2);
            int nl = wn * 64 + nt * 8 + (lane & 3) * 2;
            float2 o0, o1;
            o0.x = acc[mt][nt][0] + sbias[nl];
            o0.y = acc[mt][nt][1] + sbias[nl + 1];
            o1.x = acc[mt][nt][2] + sbias[nl];
            o1.y = acc[mt][nt][3] + sbias[nl + 1];
            *(float2*)&out[(size_t)m * Hdim + n0 + nl] = o0;
            *(float2*)&out[(size_t)(m + 8) * Hdim + n0 + nl] = o1;
        }
    }
}

// ============================================================================
// Merged dual-layer recurrence, b-split: 128 CTAs x 256 threads.
// CTA (bh, jg) owns batch half bh (32 rows) and j-range [16*jg, 16*jg+16)
// for BOTH layers. Loop s = 0..512 (R16's verified skew):
//   s < 512: h1[s+1] = tanh(xp0[s] + Whh0 . h1[s])
//   s >= 1 : h2[s-1] = tanh(bias1 + Wih1 . h1[s] + Whh1 . h2[s-2])
// 16 phases x (32b x 128k) chunks: phases 0-7 stream h1[s], 8-15 stream
// h2[s-2]. Wih1+Whh1 parts share ONE accumulator (same pre-activation).
// Whh0 + Whh1 frags in registers; Wih1 in SMEM. 4x16KB stage bufs, depth-3
// prefetch, 1 sync/phase. MAC/CTA = 4.7M on 128 SMs.
// ============================================================================
#define RNN_SMEM_BYTES 131072
#define M_WX_H   0          /* Wih1 hi 32K, lo at +32768 */
#define M_WX_L   32768
#define M_BUF(i) (65536 + (i) * 16384)
#define M_TMP_H  65536      /* temp W staging (bufs 0-3) during init */
#define M_TMP_L  98304

// stage one (32b x 128k) chunk of h (hi+lo) into a 16KB buffer.
// rows = 32 b (256B each, granule-swizzled); hi at dst, lo at dst+8192.
static __device__ __forceinline__ void stage_h32(
    const __nv_bfloat16* __restrict__ hh, const __nv_bfloat16* __restrict__ hl,
    int b0, int c, char* dst, int tid)
{
#pragma unroll
    for (int r = 0; r < 2; r++) {
        int idx = r * 256 + tid;              // 0..511
        int b = idx >> 4;                     // 0..31
        int g = idx & 15;                     // granule within 256B row
        int ph = (g & 8) | ((g ^ (b & 7)) & 7);
        uint32_t d = smem_u32(dst + b * 256 + ph * 16);
        const __nv_bfloat16* s = hh + (size_t)(b0 + b) * Hdim + c * 128 + g * 8;
        asm volatile("cp.async.cg.shared.global [%0], [%1], 16;" ::"r"(d), "l"(s));
        const __nv_bfloat16* s2 = hl + (size_t)(b0 + b) * Hdim + c * 128 + g * 8;
        asm volatile("cp.async.cg.shared.global [%0], [%1], 16;"
                     ::"r"(d + 8192), "l"(s2));
    }
}

// stage chunk q of the 16-chunk stream (q<8: h1 chunk q; q>=8: h2 chunk q-8)
static __device__ __forceinline__ void stage_q(
    const __nv_bfloat16* hh1, const __nv_bfloat16* hl1,
    const __nv_bfloat16* hh2, const __nv_bfloat16* hl2,
    int b0, int q, char* dst, int tid)
{
    if (q < 8) stage_h32(hh1, hl1, b0, q, dst, tid);
    else       stage_h32(hh2, hl2, b0, q - 8, dst, tid);
}

// load a 16x1024 W matrix into swizzled SMEM (rows 2048B, hi/lo)
static __device__ __forceinline__ void load_w_temp(
    const float* __restrict__ W, int j0, char* smraw, int hioff, int looff,
    int tid)
{
    for (int i = tid; i < 4096; i += 256) {
        int j = i >> 8;
        int col4 = i & 255;
        uint2 hi, lo;
        split_bf16(*(const float4*)&W[(size_t)(j0 + j) * Hdim + col4 * 4], hi, lo);
        int g = col4 >> 1;
        int off = j * 2048 + ((g ^ (j & 7)) << 4) + (col4 & 1) * 8;
        *(uint2*)(smraw + hioff + off) = hi;
        *(uint2*)(smraw + looff + off) = lo;
    }
}

__global__ void __launch_bounds__(256) rnn_merged_kernel(
    const float* __restrict__ xp0, const float* __restrict__ Whh0,
    const float* __restrict__ Wih1, const float* __restrict__ bi1,
    const float* __restrict__ bh1, const float* __restrict__ Whh1)
{
    extern __shared__ __align__(1024) char smraw[];
    const int tid = threadIdx.x;
    const int bid = blockIdx.x;
    const int wid = tid >> 5;
    const int lane = tid & 31;
    const int j0 = (bid & 63) * 16;
    const int b0 = (bid >> 6) * 32;

    // ldmatrix lane mappings
    const int asub = lane >> 3;
    const int arow = (asub & 1) * 8 + (lane & 7);
    const int ack = asub >> 1;
    const int brow = ((lane >> 4) & 1) * 8 + (lane & 7);
    const int bck = (lane >> 3) & 1;
    // epilogue: 2 outputs per thread (512 outputs per layer per CTA)
    const int eo = tid * 2;
    const int eb = b0 + (eo >> 4);       // global batch row
    const int ej = eo & 15;              // j within 16 (even)

    float* p_r0 = (float*)(smraw + M_BUF(0));   // rec0 partials (8w x 512)
    float* p_r1 = (float*)(smraw + M_BUF(1));   // rec1 partials

    // ---- init: Wih1 -> persistent SMEM ----
    load_w_temp(Wih1, j0, smraw, M_WX_H, M_WX_L, tid);
    // Whh0 -> temp (bufs), then registers
    load_w_temp(Whh0, j0, smraw, M_TMP_H, M_TMP_L, tid);
    __syncthreads();
    uint32_t wRh[8][4], wRl[8][4];
#pragma unroll
    for (int c = 0; c < 8; c++) {
        int gB = (c * 8 + wid) * 2 + bck;
        uint32_t sw = (uint32_t)((gB ^ (brow & 7)) << 4);
        ldsm_x4(smem_u32(smraw + M_TMP_H) + brow * 2048 + sw, wRh[c]);
        ldsm_x4(smem_u32(smraw + M_TMP_L) + brow * 2048 + sw, wRl[c]);
    }
    __syncthreads();
    // Whh1 -> temp, then registers
    load_w_temp(Whh1, j0, smraw, M_TMP_H, M_TMP_L, tid);
    __syncthreads();
    uint32_t wSh[8][4], wSl[8][4];
#pragma unroll
    for (int c = 0; c < 8; c++) {
        int gB = (c * 8 + wid) * 2 + bck;
        uint32_t sw = (uint32_t)((gB ^ (brow & 7)) << 4);
        ldsm_x4(smem_u32(smraw + M_TMP_H) + brow * 2048 + sw, wSh[c]);
        ldsm_x4(smem_u32(smraw + M_TMP_L) + brow * 2048 + sw, wSl[c]);
    }

    // zero h1[0] slot 0, h2 both slots, for owned (32b x 16j) region
    if (tid < 128) {
        int zb = b0 + (tid >> 2);
        int zj = j0 + (tid & 3) * 4;
        uint2 z2 = make_uint2(0, 0);
        *(uint2*)&g_hh1[0][(size_t)zb * Hdim + zj] = z2;
        *(uint2*)&g_hl1[0][(size_t)zb * Hdim + zj] = z2;
#pragma unroll
        for (int sl = 0; sl < 2; sl++) {
            *(uint2*)&g_hh2[sl][(size_t)zb * Hdim + zj] = z2;
            *(uint2*)&g_hl2[sl][(size_t)zb * Hdim + zj] = z2;
        }
    }
    float bias1[2];
    bias1[0] = bi1[j0 + ej] + bh1[j0 + ej];
    bias1[1] = bi1[j0 + ej + 1] + bh1[j0 + ej + 1];

    grid_sync_p(&g_bar_cnt, &g_bar_gen, 128);

#pragma unroll 1
    for (int s = 0; s <= Sdim; s++) {
        const __nv_bfloat16* hh1_in = g_hh1[s & 1];
        const __nv_bfloat16* hl1_in = g_hl1[s & 1];
        const __nv_bfloat16* hh2_in = g_hh2[s & 1];         // h2[s-2]
        const __nv_bfloat16* hl2_in = g_hl2[s & 1];
        __nv_bfloat16* hh1_out = g_hh1[(s + 1) & 1];
        __nv_bfloat16* hl1_out = g_hl1[(s + 1) & 1];
        __nv_bfloat16* hh2_out = g_hh2[(s + 1) & 1];        // h2[s-1]
        __nv_bfloat16* hl2_out = g_hl2[(s + 1) & 1];

        int tt = (s < Sdim) ? s : Sdim - 1;
        float2 xpv = *(const float2*)&xp0[((size_t)eb * Sdim + tt) * Hdim
                                          + j0 + ej];

        float accR[2][2][4], accS[2][2][4];
#pragma unroll
        for (int mt = 0; mt < 2; mt++)
#pragma unroll
            for (int nt = 0; nt < 2; nt++)
#pragma unroll
                for (int i = 0; i < 4; i++) {
                    accR[mt][nt][i] = 0.0f;
                    accS[mt][nt][i] = 0.0f;
                }

        stage_q(hh1_in, hl1_in, hh2_in, hl2_in, b0, 0, smraw + M_BUF(0), tid);
        asm volatile("cp.async.commit_group;");
        stage_q(hh1_in, hl1_in, hh2_in, hl2_in, b0, 1, smraw + M_BUF(1), tid);
        asm volatile("cp.async.commit_group;");
        stage_q(hh1_in, hl1_in, hh2_in, hl2_in, b0, 2, smraw + M_BUF(2), tid);
        asm volatile("cp.async.commit_group;");

#pragma unroll
        for (int c = 0; c < 16; c++) {
            if (c < 14)       asm volatile("cp.async.wait_group 2;");
            else if (c == 14) asm volatile("cp.async.wait_group 1;");
            else              asm volatile("cp.async.wait_group 0;");
            __syncthreads();   // chunk c visible; orders phase c-1 reads of
                               // buf (c+3)&3 before its restage below

            const uint32_t shb = smem_u32(smraw + M_BUF(c & 3));
            const uint32_t slb = shb + 8192;

            uint32_t ah[2][4], al[2][4];
            int gA = wid * 2 + ack;
#pragma unroll
            for (int mt = 0; mt < 2; mt++) {
                int row = mt * 16 + arow;
                uint32_t ph = (uint32_t)((gA & 8) | ((gA ^ (row & 7)) & 7)) << 4;
                ldsm_x4(shb + row * 256 + ph, ah[mt]);
                ldsm_x4(slb + row * 256 + ph, al[mt]);
            }

            if (c < 8) {
                // rec0 (regs) + Wih1 part of rec1 (SMEM) on the SAME h1 chunk
                int gB = (c * 8 + wid) * 2 + bck;
                uint32_t bsw = (uint32_t)((gB ^ (brow & 7)) << 4);
                uint32_t xh[4], xl[4];
                ldsm_x4(smem_u32(smraw + M_WX_H) + brow * 2048 + bsw, xh);
                ldsm_x4(smem_u32(smraw + M_WX_L) + brow * 2048 + bsw, xl);
#pragma unroll
                for (int mt = 0; mt < 2; mt++) {
                    mma16816(accR[mt][0], ah[mt], &wRh[c][0]);
                    mma16816(accR[mt][1], ah[mt], &wRh[c][2]);
                    mma16816(accR[mt][0], ah[mt], &wRl[c][0]);
                    mma16816(accR[mt][1], ah[mt], &wRl[c][2]);
                    mma16816(accR[mt][0], al[mt], &wRh[c][0]);
                    mma16816(accR[mt][1], al[mt], &wRh[c][2]);
                    mma16816(accS[mt][0], ah[mt], &xh[0]);
                    mma16816(accS[mt][1], ah[mt], &xh[2]);
                    mma16816(accS[mt][0], ah[mt], &xl[0]);
                    mma16816(accS[mt][1], ah[mt], &xl[2]);
                    mma16816(accS[mt][0], al[mt], &xh[0]);
                    mma16816(accS[mt][1], al[mt], &xh[2]);
                }
            } else {
                // Whh1 part of rec1 (regs), accumulates into SAME accS
                const int p = c - 8;
#pragma unroll
                for (int mt = 0; mt < 2; mt++) {
                    mma16816(accS[mt][0], ah[mt], &wSh[p][0]);
                    mma16816(accS[mt][1], ah[mt], &wSh[p][2]);
                    mma16816(accS[mt][0], ah[mt], &wSl[p][0]);
                    mma16816(accS[mt][1], ah[mt], &wSl[p][2]);
                    mma16816(accS[mt][0], al[mt], &wSh[p][0]);
                    mma16816(accS[mt][1], al[mt], &wSh[p][2]);
                }
            }
            if (c + 3 < 16) {
                stage_q(hh1_in, hl1_in, hh2_in, hl2_in, b0, c + 3,
                        smraw + M_BUF((c + 3) & 3), tid);
                asm volatile("cp.async.commit_group;");
            }
        }

        // partials (bufs 0/1 free: last read at phases 12/13, ordered by the
        // phase-15 top sync; writes don't touch buf3 used by phase 15)
#pragma unroll
        for (int mt = 0; mt < 2; mt++)
#pragma unroll
            for (int nt = 0; nt < 2; nt++) {
                int b = mt * 16 + (lane >> 2);
                int j = nt * 8 + (lane & 3) * 2;
                *(float2*)&p_r0[wid * 512 + b * 16 + j] =
                    make_float2(accR[mt][nt][0], accR[mt][nt][1]);
                *(float2*)&p_r0[wid * 512 + (b + 8) * 16 + j] =
                    make_float2(accR[mt][nt][2], accR[mt][nt][3]);
                *(float2*)&p_r1[wid * 512 + b * 16 + j] =
                    make_float2(accS[mt][nt][0], accS[mt][nt][1]);
                *(float2*)&p_r1[wid * 512 + (b + 8) * 16 + j] =
                    make_float2(accS[mt][nt][2], accS[mt][nt][3]);
            }
        __syncthreads();

        {
            float2 sr = *(const float2*)&p_r0[eo];
            float2 ss = *(const float2*)&p_r1[eo];
#pragma unroll
            for (int w = 1; w < 8; w++) {
                float2 q = *(const float2*)&p_r0[w * 512 + eo];
                sr.x += q.x; sr.y += q.y;
                float2 q2 = *(const float2*)&p_r1[w * 512 + eo];
                ss.x += q2.x; ss.y += q2.y;
            }
            // h1[s+1] = tanh(xp0[s] + Whh0.h1[s])
            if (s < Sdim) {
                float v0 = tanhf(sr.x + xpv.x);
                float v1 = tanhf(sr.y + xpv.y);
                unsigned hi, lo;
                split2_bf16(v0, v1, hi, lo);
                size_t ho = (size_t)eb * Hdim + j0 + ej;
                *(unsigned*)&hh1_out[ho] = hi;
                *(unsigned*)&hl1_out[ho] = lo;
            }
            // h2[s-1] = tanh(bias1 + Wih1.h1[s] + Whh1.h2[s-2])
            if (s >= 1) {
                float v0 = tanhf(ss.x + bias1[0]);
                float v1 = tanhf(ss.y + bias1[1]);
                unsigned hi, lo;
                split2_bf16(v0, v1, hi, lo);
                size_t ho = (size_t)eb * Hdim + j0 + ej;
                *(unsigned*)&hh2_out[ho] = hi;
                *(unsigned*)&hl2_out[ho] = lo;
            }
        }
        grid_sync_p(&g_bar_cnt, &g_bar_gen, 128);
    }
}

// ============================================================================
// Final FC + sigmoid: h_last = h2[511], written at s=512 into slot (512+1)&1=1
// ============================================================================
__global__ void fc_kernel(const __nv_bfloat16* __restrict__ hh,
                          const __nv_bfloat16* __restrict__ hl,
                          const float* __restrict__ fcw,
                          const float* __restrict__ fcb,
                          float* __restrict__ out)
{
    __shared__ float red[8];
    int b = blockIdx.x, tid = threadIdx.x;
    float s = 0.0f;
    for (int k = tid; k < Hdim; k += 256) {
        float h = __bfloat162float(hh[b * Hdim + k]) +
                  __bfloat162float(hl[b * Hdim + k]);
        s += h * fcw[k];
    }
#pragma unroll
    for (int o = 16; o; o >>= 1) s += __shfl_xor_sync(0xFFFFFFFFu, s, o);
    if ((tid & 31) == 0) red[tid >> 5] = s;
    __syncthreads();
    if (tid == 0) {
        float tot = 0.0f;
#pragma unroll
        for (int i = 0; i < 8; i++) tot += red[i];
        float logit = tot + fcb[0];
        out[b] = 1.0f / (1.0f + expf(-logit));
    }
}

// ============================================================================
extern "C" void kernel_launch(void* const* d_in, const int* in_sizes, int n_in,
                              void* d_out, int out_size)
{
    const float* x     = (const float*)d_in[0];
    const float* W_ih0 = (const float*)d_in[1];
    const float* W_hh0 = (const float*)d_in[2];
    const float* b_ih0 = (const float*)d_in[3];
    const float* b_hh0 = (const float*)d_in[4];
    const float* W_ih1 = (const float*)d_in[5];
    const float* W_hh1 = (const float*)d_in[6];
    const float* b_ih1 = (const float*)d_in[7];
    const float* b_hh1 = (const float*)d_in[8];
    const float* fc_w  = (const float*)d_in[9];
    const float* fc_b  = (const float*)d_in[10];
    float* out = (float*)d_out;

    float* xp;
    __nv_bfloat16 *hh2, *hl2;
    cudaGetSymbolAddress((void**)&xp, g_xp);
    cudaGetSymbolAddress((void**)&hh2, g_hh2);
    cudaGetSymbolAddress((void**)&hl2, g_hl2);

    cudaFuncSetAttribute(rnn_merged_kernel,
                         cudaFuncAttributeMaxDynamicSharedMemorySize,
                         RNN_SMEM_BYTES);
    cudaFuncSetAttribute(xproj_mma_kernel<Fdim>,
                         cudaFuncAttributeMaxDynamicSharedMemorySize, XP_SMEM);

    dim3 xgrid(8, 256);
    // layer-0 xp: rows m = b*S + t -> xp[(b*S+t)*H + j]
    xproj_mma_kernel<Fdim><<<xgrid, 256, XP_SMEM>>>(x, W_ih0, b_ih0, b_hh0, xp);
    // merged dual-layer recurrence, b-split (128 CTAs)
    rnn_merged_kernel<<<128, 256, RNN_SMEM_BYTES>>>(
        xp, W_hh0, W_ih1, b_ih1, b_hh1, W_hh1);
    // head: h2[511] written at s=512 into slot (512+1)&1 = 1
    fc_kernel<<<64, 256>>>(hh2 + Bdim * Hdim, hl2 + Bdim * Hdim, fc_w, fc_b, out);
}